// round 1
// baseline (speedup 1.0000x reference)
#include <cuda_runtime.h>

#define B_ 2
#define N_ 65536
#define C_ 256
#define H_ 8
#define D_ 64
#define S_ 64
#define TS 32            // tokens per chunk
#define PC 37            // CTAs per (b,h) pair -> 16*37 = 592 CTAs = 4 full waves
#define NCHUNK (N_/TS)   // 2048

// ---- scratch (no allocations allowed) ----
__device__ float g_T[B_*H_*S_*D_];     // unnormalized slice tokens
__device__ float g_norm[B_*H_*S_];     // slice weight sums
__device__ float g_We[H_*C_*S_];       // W_x(head) @ W_slice folded
__device__ float g_be[H_*S_];          // b_x(head) @ W_slice + b_slice

// K0: zero accumulators + fold effective slice weights
__global__ void prep_kernel(const float* __restrict__ W_x, const float* __restrict__ b_x,
                            const float* __restrict__ W_slice, const float* __restrict__ b_slice) {
    int idx = blockIdx.x * blockDim.x + threadIdx.x;   // 131072 threads
    if (idx < B_*H_*S_*D_) g_T[idx] = 0.f;
    if (idx < B_*H_*S_)    g_norm[idx] = 0.f;
    if (idx < H_*C_*S_) {
        int s = idx & 63, c = (idx >> 6) & 255, h = idx >> 14;
        float acc = 0.f;
        #pragma unroll
        for (int d = 0; d < 64; d++)
            acc += W_x[c*512 + h*64 + d] * W_slice[d*64 + s];
        g_We[idx] = acc;
    }
    if (idx < H_*S_) {
        int s = idx & 63, h = idx >> 6;
        float acc = b_slice[s];
        #pragma unroll
        for (int d = 0; d < 64; d++)
            acc += b_x[h*64 + d] * W_slice[d*64 + s];
        g_be[idx] = acc;
    }
}

// SMEM layout (floats):
//  sWe  [256][64]  @ 0       (16384)
//  sWfx [256][64]  @ 16384   (16384)
//  sX   [32][256]  @ 32768   (8192)
//  sF   [32][64]   @ 40960   (2048)
//  sW   [32][64]   @ 43008   (2048)   softmax weights
//  sBe  [64]       @ 45056
//  sBfx [64]       @ 45120
// total 45184 floats = 180736 B
#define SMEM_FLOATS 45184

extern __shared__ float sm[];

__global__ void __launch_bounds__(256, 1)
fused_kernel(const float* __restrict__ x, const float* __restrict__ W_fx,
             const float* __restrict__ b_fx, const float* __restrict__ temperature) {
    float* sWe  = sm;
    float* sWfx = sm + 16384;
    float* sX   = sm + 32768;
    float* sF   = sm + 40960;
    float* sW   = sm + 43008;
    float* sBe  = sm + 45056;
    float* sBfx = sm + 45120;

    const int tid  = threadIdx.x;
    const int pair = blockIdx.x / PC;      // b*8 + h
    const int cidx = blockIdx.x % PC;
    const int b = pair >> 3, h = pair & 7;

    // load per-head weights into SMEM (resident for whole kernel)
    for (int g = tid; g < 4096; g += 256) {
        ((float4*)sWe)[g] = ((const float4*)(g_We + h*16384))[g];
        int k = g >> 4, d4 = g & 15;
        *(float4*)&sWfx[k*64 + d4*4] = *(const float4*)&W_fx[k*512 + h*64 + d4*4];
    }
    if (tid < 64) {
        sBe[tid]  = g_be[h*64 + tid];
        sBfx[tid] = b_fx[h*64 + tid];
    }
    float tmp = temperature[h];
    tmp = fminf(fmaxf(tmp, 0.5f), 5.0f);
    const float invT = 1.0f / tmp;
    __syncthreads();

    const int warp = tid >> 5, lane = tid & 31;
    const int t0 = warp * 4;
    const int dcol = tid & 63, sbase = (tid >> 6) * 16;

    float accT[16];
    #pragma unroll
    for (int i = 0; i < 16; i++) accT[i] = 0.f;
    float accN = 0.f;

    const float* xbase = x + (size_t)b * N_ * C_;

    for (int chunk = cidx; chunk < NCHUNK; chunk += PC) {
        const float* xp = xbase + (size_t)chunk * TS * C_;

        // phase 1: load x tile (coalesced float4)
        for (int g = tid; g < 2048; g += 256)
            ((float4*)sX)[g] = ((const float4*)xp)[g];
        __syncthreads();

        // phase 2: per-warp, 4 tokens x (64 logit cols + 64 f cols)
        float accS[4][2], accF[4][2];
        #pragma unroll
        for (int i = 0; i < 4; i++) { accS[i][0]=accS[i][1]=accF[i][0]=accF[i][1]=0.f; }
        #pragma unroll 4
        for (int k = 0; k < 256; k++) {
            float2 we = *(const float2*)&sWe[k*64 + 2*lane];
            float2 wf = *(const float2*)&sWfx[k*64 + 2*lane];
            #pragma unroll
            for (int i = 0; i < 4; i++) {
                float xv = sX[(t0+i)*256 + k];
                accS[i][0] += xv * we.x;  accS[i][1] += xv * we.y;
                accF[i][0] += xv * wf.x;  accF[i][1] += xv * wf.y;
            }
        }

        // store f (+bias)
        float bf0 = sBfx[2*lane], bf1 = sBfx[2*lane+1];
        float be0 = sBe[2*lane],  be1 = sBe[2*lane+1];
        #pragma unroll
        for (int i = 0; i < 4; i++)
            *(float2*)&sF[(t0+i)*64 + 2*lane] = make_float2(accF[i][0]+bf0, accF[i][1]+bf1);

        // phase 3: softmax across 64 slices (spread 2-per-lane over the warp)
        #pragma unroll
        for (int i = 0; i < 4; i++) {
            float l0 = (accS[i][0] + be0) * invT;
            float l1 = (accS[i][1] + be1) * invT;
            float m = fmaxf(l0, l1);
            #pragma unroll
            for (int off = 16; off; off >>= 1)
                m = fmaxf(m, __shfl_xor_sync(0xffffffffu, m, off));
            float e0 = __expf(l0 - m), e1 = __expf(l1 - m);
            float ss = e0 + e1;
            #pragma unroll
            for (int off = 16; off; off >>= 1)
                ss += __shfl_xor_sync(0xffffffffu, ss, off);
            float inv = __frcp_rn(ss);
            *(float2*)&sW[(t0+i)*64 + 2*lane] = make_float2(e0*inv, e1*inv);
        }
        __syncthreads();

        // phase 4: rank-32 update of T[s][d] (16 s-rows per thread, in registers)
        #pragma unroll 4
        for (int t = 0; t < 32; t++) {
            float fv = sF[t*64 + dcol];
            const float4* wr = (const float4*)&sW[t*64 + sbase];
            float4 w0 = wr[0], w1 = wr[1], w2 = wr[2], w3 = wr[3];
            accT[0]  += w0.x*fv; accT[1]  += w0.y*fv; accT[2]  += w0.z*fv; accT[3]  += w0.w*fv;
            accT[4]  += w1.x*fv; accT[5]  += w1.y*fv; accT[6]  += w1.z*fv; accT[7]  += w1.w*fv;
            accT[8]  += w2.x*fv; accT[9]  += w2.y*fv; accT[10] += w2.z*fv; accT[11] += w2.w*fv;
            accT[12] += w3.x*fv; accT[13] += w3.y*fv; accT[14] += w3.z*fv; accT[15] += w3.w*fv;
        }
        if (tid < 64) {
            #pragma unroll
            for (int t = 0; t < 32; t++) accN += sW[t*64 + tid];
        }
        __syncthreads();
    }

    // flush partials
    float* dst = g_T + pair * 4096;
    #pragma unroll
    for (int i = 0; i < 16; i++)
        atomicAdd(&dst[(sbase + i)*64 + dcol], accT[i]);
    if (tid < 64) atomicAdd(&g_norm[pair*64 + tid], accN);
}

// K2: final normalization into the output buffer
__global__ void norm_kernel(float* __restrict__ out) {
    int idx = blockIdx.x * blockDim.x + threadIdx.x;   // 65536
    int ps = idx >> 6;                                 // pair*64 + s
    out[idx] = g_T[idx] / (g_norm[ps] + 0.01f);
}

extern "C" void kernel_launch(void* const* d_in, const int* in_sizes, int n_in,
                              void* d_out, int out_size) {
    const float* x    = (const float*)d_in[0];
    const float* W_x  = (const float*)d_in[1];
    const float* b_x  = (const float*)d_in[2];
    const float* W_fx = (const float*)d_in[3];
    const float* b_fx = (const float*)d_in[4];
    const float* W_s  = (const float*)d_in[5];
    const float* b_s  = (const float*)d_in[6];
    const float* temp = (const float*)d_in[7];
    float* out = (float*)d_out;

    cudaFuncSetAttribute(fused_kernel, cudaFuncAttributeMaxDynamicSharedMemorySize,
                         SMEM_FLOATS * (int)sizeof(float));

    prep_kernel<<<512, 256>>>(W_x, b_x, W_s, b_s);
    fused_kernel<<<16 * PC, 256, SMEM_FLOATS * sizeof(float)>>>(x, W_fx, b_fx, temp);
    norm_kernel<<<256, 256>>>(out);
}

// round 2
// speedup vs baseline: 1.0040x; 1.0040x over previous
#include <cuda_runtime.h>

#define B_ 2
#define N_ 65536
#define C_ 256
#define H_ 8
#define D_ 64
#define S_ 64
#define TS 32            // tokens per chunk
#define PC 37            // CTAs per (b,h) pair -> 16*37 = 592 CTAs = 4 full waves
#define NCHUNK (N_/TS)   // 2048

// ---- scratch (no allocations allowed) ----
__device__ float g_T[B_*H_*S_*D_];     // unnormalized slice tokens
__device__ float g_norm[B_*H_*S_];     // slice weight sums
__device__ float g_We[H_*C_*S_];       // W_x(head) @ W_slice folded
__device__ float g_be[H_*S_];          // b_x(head) @ W_slice + b_slice

// K0: zero accumulators + fold effective slice weights
__global__ void prep_kernel(const float* __restrict__ W_x, const float* __restrict__ b_x,
                            const float* __restrict__ W_slice, const float* __restrict__ b_slice) {
    int idx = blockIdx.x * blockDim.x + threadIdx.x;   // 131072 threads
    if (idx < B_*H_*S_*D_) g_T[idx] = 0.f;
    if (idx < B_*H_*S_)    g_norm[idx] = 0.f;
    if (idx < H_*C_*S_) {
        int s = idx & 63, c = (idx >> 6) & 255, h = idx >> 14;
        float acc = 0.f;
        #pragma unroll
        for (int d = 0; d < 64; d++)
            acc += W_x[c*512 + h*64 + d] * W_slice[d*64 + s];
        g_We[idx] = acc;
    }
    if (idx < H_*S_) {
        int s = idx & 63, h = idx >> 6;
        float acc = b_slice[s];
        #pragma unroll
        for (int d = 0; d < 64; d++)
            acc += b_x[h*64 + d] * W_slice[d*64 + s];
        g_be[idx] = acc;
    }
}

// SMEM layout (floats):
//  sWe  [256][64]  @ 0       (16384)
//  sWfx [256][64]  @ 16384   (16384)
//  sX   [32][256]  @ 32768   (8192)
//  sF   [32][64]   @ 40960   (2048)
//  sW   [32][64]   @ 43008   (2048)   softmax weights
//  sBe  [64]       @ 45056
//  sBfx [64]       @ 45120
// total 45184 floats = 180736 B
#define SMEM_FLOATS 45184

extern __shared__ float sm[];

__global__ void __launch_bounds__(256, 1)
fused_kernel(const float* __restrict__ x, const float* __restrict__ W_fx,
             const float* __restrict__ b_fx, const float* __restrict__ temperature) {
    float* sWe  = sm;
    float* sWfx = sm + 16384;
    float* sX   = sm + 32768;
    float* sF   = sm + 40960;
    float* sW   = sm + 43008;
    float* sBe  = sm + 45056;
    float* sBfx = sm + 45120;

    const int tid  = threadIdx.x;
    const int pair = blockIdx.x / PC;      // b*8 + h
    const int cidx = blockIdx.x % PC;
    const int b = pair >> 3, h = pair & 7;

    // load per-head weights into SMEM (resident for whole kernel)
    for (int g = tid; g < 4096; g += 256) {
        ((float4*)sWe)[g] = ((const float4*)(g_We + h*16384))[g];
        int k = g >> 4, d4 = g & 15;
        *(float4*)&sWfx[k*64 + d4*4] = *(const float4*)&W_fx[k*512 + h*64 + d4*4];
    }
    if (tid < 64) {
        sBe[tid]  = g_be[h*64 + tid];
        sBfx[tid] = b_fx[h*64 + tid];
    }
    float tmp = temperature[h];
    tmp = fminf(fmaxf(tmp, 0.5f), 5.0f);
    const float invT = 1.0f / tmp;
    __syncthreads();

    const int warp = tid >> 5, lane = tid & 31;
    const int t0 = warp * 4;
    const int dcol = tid & 63, sbase = (tid >> 6) * 16;

    float accT[16];
    #pragma unroll
    for (int i = 0; i < 16; i++) accT[i] = 0.f;
    float accN = 0.f;

    const float* xbase = x + (size_t)b * N_ * C_;

    for (int chunk = cidx; chunk < NCHUNK; chunk += PC) {
        const float* xp = xbase + (size_t)chunk * TS * C_;

        // phase 1: load x tile (coalesced float4)
        for (int g = tid; g < 2048; g += 256)
            ((float4*)sX)[g] = ((const float4*)xp)[g];
        __syncthreads();

        // phase 2: per-warp, 4 tokens x (64 logit cols + 64 f cols)
        float accS[4][2], accF[4][2];
        #pragma unroll
        for (int i = 0; i < 4; i++) { accS[i][0]=accS[i][1]=accF[i][0]=accF[i][1]=0.f; }
        #pragma unroll 4
        for (int k = 0; k < 256; k++) {
            float2 we = *(const float2*)&sWe[k*64 + 2*lane];
            float2 wf = *(const float2*)&sWfx[k*64 + 2*lane];
            #pragma unroll
            for (int i = 0; i < 4; i++) {
                float xv = sX[(t0+i)*256 + k];
                accS[i][0] += xv * we.x;  accS[i][1] += xv * we.y;
                accF[i][0] += xv * wf.x;  accF[i][1] += xv * wf.y;
            }
        }

        // store f (+bias)
        float bf0 = sBfx[2*lane], bf1 = sBfx[2*lane+1];
        float be0 = sBe[2*lane],  be1 = sBe[2*lane+1];
        #pragma unroll
        for (int i = 0; i < 4; i++)
            *(float2*)&sF[(t0+i)*64 + 2*lane] = make_float2(accF[i][0]+bf0, accF[i][1]+bf1);

        // phase 3: softmax across 64 slices (spread 2-per-lane over the warp)
        #pragma unroll
        for (int i = 0; i < 4; i++) {
            float l0 = (accS[i][0] + be0) * invT;
            float l1 = (accS[i][1] + be1) * invT;
            float m = fmaxf(l0, l1);
            #pragma unroll
            for (int off = 16; off; off >>= 1)
                m = fmaxf(m, __shfl_xor_sync(0xffffffffu, m, off));
            float e0 = __expf(l0 - m), e1 = __expf(l1 - m);
            float ss = e0 + e1;
            #pragma unroll
            for (int off = 16; off; off >>= 1)
                ss += __shfl_xor_sync(0xffffffffu, ss, off);
            float inv = __frcp_rn(ss);
            *(float2*)&sW[(t0+i)*64 + 2*lane] = make_float2(e0*inv, e1*inv);
        }
        __syncthreads();

        // phase 4: rank-32 update of T[s][d] (16 s-rows per thread, in registers)
        #pragma unroll 4
        for (int t = 0; t < 32; t++) {
            float fv = sF[t*64 + dcol];
            const float4* wr = (const float4*)&sW[t*64 + sbase];
            float4 w0 = wr[0], w1 = wr[1], w2 = wr[2], w3 = wr[3];
            accT[0]  += w0.x*fv; accT[1]  += w0.y*fv; accT[2]  += w0.z*fv; accT[3]  += w0.w*fv;
            accT[4]  += w1.x*fv; accT[5]  += w1.y*fv; accT[6]  += w1.z*fv; accT[7]  += w1.w*fv;
            accT[8]  += w2.x*fv; accT[9]  += w2.y*fv; accT[10] += w2.z*fv; accT[11] += w2.w*fv;
            accT[12] += w3.x*fv; accT[13] += w3.y*fv; accT[14] += w3.z*fv; accT[15] += w3.w*fv;
        }
        if (tid < 64) {
            #pragma unroll
            for (int t = 0; t < 32; t++) accN += sW[t*64 + tid];
        }
        __syncthreads();
    }

    // flush partials
    float* dst = g_T + pair * 4096;
    #pragma unroll
    for (int i = 0; i < 16; i++)
        atomicAdd(&dst[(sbase + i)*64 + dcol], accT[i]);
    if (tid < 64) atomicAdd(&g_norm[pair*64 + tid], accN);
}

// K2: final normalization into the output buffer
__global__ void norm_kernel(float* __restrict__ out) {
    int idx = blockIdx.x * blockDim.x + threadIdx.x;   // 65536
    int ps = idx >> 6;                                 // pair*64 + s
    out[idx] = g_T[idx] / (g_norm[ps] + 0.01f);
}

extern "C" void kernel_launch(void* const* d_in, const int* in_sizes, int n_in,
                              void* d_out, int out_size) {
    const float* x    = (const float*)d_in[0];
    const float* W_x  = (const float*)d_in[1];
    const float* b_x  = (const float*)d_in[2];
    const float* W_fx = (const float*)d_in[3];
    const float* b_fx = (const float*)d_in[4];
    const float* W_s  = (const float*)d_in[5];
    const float* b_s  = (const float*)d_in[6];
    const float* temp = (const float*)d_in[7];
    float* out = (float*)d_out;

    cudaFuncSetAttribute(fused_kernel, cudaFuncAttributeMaxDynamicSharedMemorySize,
                         SMEM_FLOATS * (int)sizeof(float));

    prep_kernel<<<512, 256>>>(W_x, b_x, W_s, b_s);
    fused_kernel<<<16 * PC, 256, SMEM_FLOATS * sizeof(float)>>>(x, W_fx, b_fx, temp);
    norm_kernel<<<256, 256>>>(out);
}